// round 11
// baseline (speedup 1.0000x reference)
#include <cuda_runtime.h>
#include <cuda_bf16.h>
#include <mma.h>
#include <math.h>

using namespace nvcuda;

// Problem constants
#define BB 64
#define WW 16
#define CC 64
#define TT 1024
#define DE 64
#define NBW 1024           // B*W
#define NROWS 65536        // B*W*C
#define XR_ELEMS 67108864  // B*C*W*T

// -------- device scratch (no allocations allowed) --------
__device__ float g_stat[NROWS];   // [bw][c]
__device__ float g_Z[CC * DE];    // [c][d]
__device__ float g_A2[CC * CC];   // A_final @ A_final

// ================= Kernel 1: per-row stats =================
__global__ void k_stats(const float* __restrict__ x) {
    int warp = (blockIdx.x * blockDim.x + threadIdx.x) >> 5;
    int lane = threadIdx.x & 31;
    if (warp >= NROWS) return;
    const float4* p = reinterpret_cast<const float4*>(x) + (size_t)warp * 256;
    float s1 = 0.f, s2 = 0.f;
#pragma unroll
    for (int k = 0; k < 8; k++) {
        float4 v = p[lane + 32 * k];
        s1 += (v.x + v.y) + (v.z + v.w);
        s2 += v.x * v.x + v.y * v.y + v.z * v.z + v.w * v.w;
    }
#pragma unroll
    for (int off = 16; off > 0; off >>= 1) {
        s1 += __shfl_xor_sync(0xffffffffu, s1, off);
        s2 += __shfl_xor_sync(0xffffffffu, s2, off);
    }
    if (lane == 0) g_stat[warp] = 0.5f * (s1 + s2) * (1.0f / 1024.0f);
}

// ================= Kernel 2: Z_mean[c][d] =================
__global__ void k_zmean(const float* __restrict__ Wp) {
    __shared__ float scol[NBW];
    __shared__ float swp[DE];
    __shared__ float part[256];
    int c = blockIdx.x;
    int tid = threadIdx.x;
    if (tid < DE) swp[tid] = Wp[tid];
    for (int i = tid; i < NBW; i += 256) scol[i] = g_stat[i * CC + c];
    __syncthreads();
    int d = tid & 63, grp = tid >> 6;
    float w = swp[d];
    float s = 0.f;
    for (int bw = grp; bw < NBW; bw += 4) s += tanhf(scol[bw] * w);
    part[tid] = s;
    __syncthreads();
    if (tid < 64) {
        float z = (part[tid] + part[tid + 64] + part[tid + 128] + part[tid + 192]) *
                  (1.0f / 1024.0f);
        g_Z[c * DE + tid] = z;
    }
}

// ================= Kernel 3: graph build (single block, 1024 thr) =================
__device__ __forceinline__ unsigned rotl32(unsigned v, int s) {
    return (v << s) | (v >> (32 - s));
}
__device__ __forceinline__ void threefry_0_42(unsigned c0, unsigned c1,
                                              unsigned& o0, unsigned& o1) {
    const unsigned ks0 = 0u, ks1 = 42u, ks2 = 0u ^ 42u ^ 0x1BD11BDAu;
    unsigned x0 = c0 + ks0, x1 = c1 + ks1;
#define TF_RND(r) { x0 += x1; x1 = rotl32(x1, r); x1 ^= x0; }
    TF_RND(13) TF_RND(15) TF_RND(26) TF_RND(6)  x0 += ks1; x1 += ks2 + 1u;
    TF_RND(17) TF_RND(29) TF_RND(16) TF_RND(24) x0 += ks2; x1 += ks0 + 2u;
    TF_RND(13) TF_RND(15) TF_RND(26) TF_RND(6)  x0 += ks0; x1 += ks1 + 3u;
    TF_RND(17) TF_RND(29) TF_RND(16) TF_RND(24) x0 += ks1; x1 += ks2 + 4u;
    TF_RND(13) TF_RND(15) TF_RND(26) TF_RND(6)  x0 += ks2; x1 += ks0 + 5u;
#undef TF_RND
    o0 = x0; o1 = x1;
}
// Partitionable threefry: counter (0, idx); sample = XOR-fold of output words.
__device__ __forceinline__ float gumbel_at(int idx) {
    unsigned o0, o1;
    threefry_0_42(0u, (unsigned)idx, o0, o1);
    unsigned bits = o0 ^ o1;
    float u = __uint_as_float((bits >> 9) | 0x3f800000u) - 1.0f;
    const float tiny = 1.17549435e-38f;
    float r = fmaxf(tiny, u + tiny);
    return -logf(-logf(r));
}
__device__ __forceinline__ float gelu_exact(float v) {
    return 0.5f * v * (1.0f + erff(v * 0.70710678118654752f));
}
__device__ __forceinline__ float softplus_f(float v) {
    return fmaxf(v, 0.f) + log1pf(expf(-fabsf(v)));
}

#define GNT 1024
#define EPT 4

__global__ void __launch_bounds__(GNT) k_graph(
        const float* __restrict__ w1, const float* __restrict__ b1,
        const float* __restrict__ w2, const float* __restrict__ b2,
        const float* __restrict__ pbeta, const float* __restrict__ pgamma,
        const float* __restrict__ ptemp, float* __restrict__ outA) {
    __shared__ float sA[4096];
    __shared__ float sS[4096];
    __shared__ float ssq[64];
    __shared__ float sdinv[64];
    __shared__ unsigned long long smask[64];
    __shared__ float sw1[16], sb1[16], sw2[16];
    int tid = threadIdx.x;
    if (tid < 16) { sw1[tid] = w1[tid]; sb1[tid] = b1[tid]; sw2[tid] = w2[tid]; }
    float beta = *pbeta, gamma = *pgamma, b2v = *b2;
    float invt = 1.0f / fmaxf(*ptemp, 1e-6f);

#pragma unroll
    for (int k = 0; k < EPT; k++) sS[tid + GNT * k] = g_Z[tid + GNT * k];
    __syncthreads();
    if (tid < 64) {
        float s = 0.f;
#pragma unroll
        for (int m = 0; m < 64; m++) { float z = sS[tid * 64 + m]; s += z * z; }
        ssq[tid] = s;
    }
    __syncthreads();

    float d2r[EPT];
#pragma unroll
    for (int k = 0; k < EPT; k++) {
        int e = tid + GNT * k, i = e >> 6, j = e & 63;
        float dot = 0.f;
        for (int m = 0; m < 64; m++) dot += sS[i * 64 + m] * sS[j * 64 + m];
        float v = ssq[i] + ssq[j] - 2.0f * dot;
        d2r[k] = fmaxf(v, 0.f) * 0.5f;
        sA[e] = (i == j) ? 1.f : 0.f;
    }
    __syncthreads();

    for (int step = 0; step < 2; step++) {
#pragma unroll
        for (int k = 0; k < EPT; k++) {
            int e = tid + GNT * k;
            float a = sA[e] - 0.2f * d2r[k];
            float s = b2v;
#pragma unroll
            for (int m = 0; m < 16; m++) {
                float h = gelu_exact(fmaf(a, sw1[m], sb1[m]));
                s = fmaf(h, sw2[m], s);
            }
            a = a + beta * (softplus_f(s) * gamma);
            sA[e] = a;
        }
        __syncthreads();
        float r1[EPT], r2[EPT];
#pragma unroll
        for (int k = 0; k < EPT; k++) {
            int e = tid + GNT * k, i = e >> 6, j = e & 63;
            r1[k] = sA[e]; r2[k] = sA[j * 64 + i];
        }
        __syncthreads();
#pragma unroll
        for (int k = 0; k < EPT; k++) {
            int e = tid + GNT * k, i = e >> 6, j = e & 63;
            float v = 0.5f * (r1[k] + r2[k]);
            sA[e] = fmaxf(v, 0.f) + ((i == j) ? 1.f : 0.f);
        }
        __syncthreads();
    }

#pragma unroll
    for (int k = 0; k < EPT; k++) {
        int e = tid + GNT * k;
        sS[e] = (sA[e] + gumbel_at(e)) * invt;
    }
    __syncthreads();

    {   // warp-parallel top-16, 32 warps x 2 rows
        int warp = tid >> 5, lane = tid & 31;
        const float NEG_INF = __int_as_float(0xff800000);
#pragma unroll
        for (int rr = 0; rr < 2; rr++) {
            int r = warp * 2 + rr;
            float v0 = sS[r * 64 + lane];
            float v1 = sS[r * 64 + 32 + lane];
            bool p0 = false, p1 = false;
            for (int p = 0; p < 16; p++) {
                float bv; int bi;
                if (v0 >= v1) { bv = v0; bi = lane; }
                else          { bv = v1; bi = lane + 32; }
#pragma unroll
                for (int off = 16; off > 0; off >>= 1) {
                    float ov = __shfl_xor_sync(0xffffffffu, bv, off);
                    int   oi = __shfl_xor_sync(0xffffffffu, bi, off);
                    if (ov > bv || (ov == bv && oi < bi)) { bv = ov; bi = oi; }
                }
                if (bi == lane)           { p0 = true; v0 = NEG_INF; }
                else if (bi == lane + 32) { p1 = true; v1 = NEG_INF; }
            }
            unsigned lo = __ballot_sync(0xffffffffu, p0);
            unsigned hi = __ballot_sync(0xffffffffu, p1);
            if (lane == 0)
                smask[r] = (unsigned long long)lo | ((unsigned long long)hi << 32);
        }
    }
    __syncthreads();
#pragma unroll
    for (int k = 0; k < EPT; k++) {
        int e = tid + GNT * k, i = e >> 6, j = e & 63;
        if (!((smask[i] >> j) & 1ull)) sA[e] = 0.f;
    }
    __syncthreads();
    {
        float r1[EPT], r2[EPT];
#pragma unroll
        for (int k = 0; k < EPT; k++) {
            int e = tid + GNT * k, i = e >> 6, j = e & 63;
            r1[k] = sA[e]; r2[k] = sA[j * 64 + i];
        }
        __syncthreads();
#pragma unroll
        for (int k = 0; k < EPT; k++) {
            int e = tid + GNT * k, i = e >> 6, j = e & 63;
            float v = fmaxf(0.5f * (r1[k] + r2[k]), 0.f) + ((i == j) ? 1.f : 0.f);
            sA[e] = v;
        }
        __syncthreads();
    }
    if (tid < 64) {
        float s = 0.f;
        for (int j = 0; j < 64; j++) s += sA[tid * 64 + j];
        sdinv[tid] = rsqrtf(fmaxf(s, 1e-6f));
    }
    __syncthreads();
#pragma unroll
    for (int k = 0; k < EPT; k++) {
        int e = tid + GNT * k, i = e >> 6, j = e & 63;
        float v = sdinv[i] * sA[e] * sdinv[j] + ((i == j) ? 1.f : 0.f);
        sA[e] = v;
        outA[e] = v;
    }
    __syncthreads();
#pragma unroll
    for (int k = 0; k < EPT; k++) {
        int e = tid + GNT * k, i = e >> 6, j = e & 63;
        float s = 0.f;
        for (int m = 0; m < 64; m++) s += sA[i * 64 + m] * sA[m * 64 + j];
        g_A2[e] = s;
    }
}

// ================= Kernel 4: out = A2 @ x via WMMA bf16-split =================
// Block = one (bw, 256t) tile.
// A_stack[128x64] bf16 row-major in smem: rows 0-63 = hi(A2), 64-127 = lo(A2-hi).
// x tile -> bf16 hi & lo planes [64 x 256] row-major.
// D = A_stack @ xh + A_stack @ xl (wmma 16x16x16, f32 acc);
// out rows c = D[c] + D[c+64] (fragment-wise add), store_matrix_sync to gmem.
// smem: A 16 KB @0, xh 32 KB @16K, xl 32 KB @48K -> 80 KB dynamic.
#define SMP_A  0
#define SMP_XH 16384
#define SMP_XL 49152
#define SMP_TOT 81920

__global__ void __launch_bounds__(256) k_prop_wmma(const float* __restrict__ x,
                                                   float* __restrict__ out) {
    extern __shared__ char smem[];
    __nv_bfloat16* sA = reinterpret_cast<__nv_bfloat16*>(smem + SMP_A);
    __nv_bfloat16* sXH = reinterpret_cast<__nv_bfloat16*>(smem + SMP_XH);
    __nv_bfloat16* sXL = reinterpret_cast<__nv_bfloat16*>(smem + SMP_XL);
    int tid = threadIdx.x, warp = tid >> 5;
    int bw = blockIdx.x >> 2, tgrp = (blockIdx.x & 3) << 8;
    const float* xt = x + ((size_t)bw << 16) + tgrp;

    // A conversion: 4096 elements
#pragma unroll
    for (int k = 0; k < 16; k++) {
        int idx = tid + 256 * k;
        int c = idx >> 6, j = idx & 63;
        float a = g_A2[idx];
        __nv_bfloat16 ah = __float2bfloat16(a);
        __nv_bfloat16 al = __float2bfloat16(a - __bfloat162float(ah));
        sA[c * 64 + j] = ah;
        sA[(c + 64) * 64 + j] = al;
    }

    // x conversion: 4096 float4 -> hi/lo bf16 planes
#pragma unroll
    for (int r = 0; r < 16; r++) {
        int idx = tid + 256 * r;
        int j = idx >> 6, f4i = idx & 63;
        float4 v = *reinterpret_cast<const float4*>(xt + (size_t)j * 1024 + f4i * 4);
        __nv_bfloat16 h0 = __float2bfloat16(v.x), h1 = __float2bfloat16(v.y);
        __nv_bfloat16 h2 = __float2bfloat16(v.z), h3 = __float2bfloat16(v.w);
        __nv_bfloat16 l0 = __float2bfloat16(v.x - __bfloat162float(h0));
        __nv_bfloat16 l1 = __float2bfloat16(v.y - __bfloat162float(h1));
        __nv_bfloat16 l2 = __float2bfloat16(v.z - __bfloat162float(h2));
        __nv_bfloat16 l3 = __float2bfloat16(v.w - __bfloat162float(h3));
        __nv_bfloat162* ph = reinterpret_cast<__nv_bfloat162*>(sXH + j * 256 + f4i * 4);
        __nv_bfloat162* pl = reinterpret_cast<__nv_bfloat162*>(sXL + j * 256 + f4i * 4);
        ph[0] = __halves2bfloat162(h0, h1);
        ph[1] = __halves2bfloat162(h2, h3);
        pl[0] = __halves2bfloat162(l0, l1);
        pl[1] = __halves2bfloat162(l2, l3);
    }
    __syncthreads();

    size_t obase = (size_t)(bw >> 4) * 1048576 + (size_t)(bw & 15) * 1024 + tgrp;

    // Each warp: 2 N-tiles of 16 t
#pragma unroll
    for (int nt2 = 0; nt2 < 2; nt2++) {
        int n0 = (warp * 2 + nt2) * 16;
        wmma::fragment<wmma::accumulator, 16, 16, 16, float> acc[8];
#pragma unroll
        for (int mt = 0; mt < 8; mt++) wmma::fill_fragment(acc[mt], 0.0f);

#pragma unroll
        for (int k = 0; k < 4; k++) {
            wmma::fragment<wmma::matrix_a, 16, 16, 16, __nv_bfloat16, wmma::row_major> af[8];
#pragma unroll
            for (int mt = 0; mt < 8; mt++)
                wmma::load_matrix_sync(af[mt], sA + (mt * 16) * 64 + k * 16, 64);

            wmma::fragment<wmma::matrix_b, 16, 16, 16, __nv_bfloat16, wmma::row_major> bh, bl;
            wmma::load_matrix_sync(bh, sXH + (k * 16) * 256 + n0, 256);
            wmma::load_matrix_sync(bl, sXL + (k * 16) * 256 + n0, 256);
#pragma unroll
            for (int mt = 0; mt < 8; mt++) wmma::mma_sync(acc[mt], af[mt], bh, acc[mt]);
#pragma unroll
            for (int mt = 0; mt < 8; mt++) wmma::mma_sync(acc[mt], af[mt], bl, acc[mt]);
        }

        // sum hi-part rows (mt) and lo-part rows (mt+4); store to gmem
#pragma unroll
        for (int mt = 0; mt < 4; mt++) {
#pragma unroll
            for (int e = 0; e < acc[mt].num_elements; e++)
                acc[mt].x[e] += acc[mt + 4].x[e];
            wmma::store_matrix_sync(out + obase + (size_t)(mt * 16) * 16384 + n0,
                                    acc[mt], 16384, wmma::mem_row_major);
        }
    }
}

// ================= launch =================
extern "C" void kernel_launch(void* const* d_in, const int* in_sizes, int n_in,
                              void* d_out, int out_size) {
    const float* x     = (const float*)d_in[0];
    const float* Wp    = (const float*)d_in[1];
    const float* w1    = (const float*)d_in[2];
    const float* b1    = (const float*)d_in[3];
    const float* w2    = (const float*)d_in[4];
    const float* b2    = (const float*)d_in[5];
    const float* beta  = (const float*)d_in[6];
    const float* gamma = (const float*)d_in[7];
    const float* temp  = (const float*)d_in[8];
    float* out = (float*)d_out;

    static int inited = 0;
    if (!inited) {
        cudaFuncSetAttribute(k_prop_wmma, cudaFuncAttributeMaxDynamicSharedMemorySize, SMP_TOT);
        inited = 1;
    }

    k_stats<<<8192, 256>>>(x);
    k_zmean<<<64, 256>>>(Wp);
    k_graph<<<1, GNT>>>(w1, b1, w2, b2, beta, gamma, temp, out + XR_ELEMS);
    k_prop_wmma<<<4096, 256, SMP_TOT>>>(x, out);
}

// round 13
// speedup vs baseline: 1.7311x; 1.7311x over previous
#include <cuda_runtime.h>
#include <cuda_bf16.h>
#include <mma.h>
#include <math.h>

using namespace nvcuda;

// Problem constants
#define BB 64
#define WW 16
#define CC 64
#define TT 1024
#define DE 64
#define NBW 1024           // B*W
#define NROWS 65536        // B*W*C
#define XR_ELEMS 67108864  // B*C*W*T

// -------- device scratch (no allocations allowed) --------
__device__ float g_stat[NROWS];   // [bw][c]
__device__ float g_Z[CC * DE];    // [c][d]
__device__ float g_A2[CC * CC];   // A_final @ A_final

// ================= Kernel 1: per-row stats =================
__global__ void k_stats(const float* __restrict__ x) {
    int warp = (blockIdx.x * blockDim.x + threadIdx.x) >> 5;
    int lane = threadIdx.x & 31;
    if (warp >= NROWS) return;
    const float4* p = reinterpret_cast<const float4*>(x) + (size_t)warp * 256;
    float s1 = 0.f, s2 = 0.f;
#pragma unroll
    for (int k = 0; k < 8; k++) {
        float4 v = p[lane + 32 * k];
        s1 += (v.x + v.y) + (v.z + v.w);
        s2 += v.x * v.x + v.y * v.y + v.z * v.z + v.w * v.w;
    }
#pragma unroll
    for (int off = 16; off > 0; off >>= 1) {
        s1 += __shfl_xor_sync(0xffffffffu, s1, off);
        s2 += __shfl_xor_sync(0xffffffffu, s2, off);
    }
    if (lane == 0) g_stat[warp] = 0.5f * (s1 + s2) * (1.0f / 1024.0f);
}

// ================= Kernel 2: Z_mean[c][d] =================
__global__ void k_zmean(const float* __restrict__ Wp) {
    __shared__ float scol[NBW];
    __shared__ float swp[DE];
    __shared__ float part[256];
    int c = blockIdx.x;
    int tid = threadIdx.x;
    if (tid < DE) swp[tid] = Wp[tid];
    for (int i = tid; i < NBW; i += 256) scol[i] = g_stat[i * CC + c];
    __syncthreads();
    int d = tid & 63, grp = tid >> 6;
    float w = swp[d];
    float s = 0.f;
    for (int bw = grp; bw < NBW; bw += 4) s += tanhf(scol[bw] * w);
    part[tid] = s;
    __syncthreads();
    if (tid < 64) {
        float z = (part[tid] + part[tid + 64] + part[tid + 128] + part[tid + 192]) *
                  (1.0f / 1024.0f);
        g_Z[c * DE + tid] = z;
    }
}

// ================= Kernel 3: graph build (single block, 1024 thr) =================
__device__ __forceinline__ unsigned rotl32(unsigned v, int s) {
    return (v << s) | (v >> (32 - s));
}
__device__ __forceinline__ void threefry_0_42(unsigned c0, unsigned c1,
                                              unsigned& o0, unsigned& o1) {
    const unsigned ks0 = 0u, ks1 = 42u, ks2 = 0u ^ 42u ^ 0x1BD11BDAu;
    unsigned x0 = c0 + ks0, x1 = c1 + ks1;
#define TF_RND(r) { x0 += x1; x1 = rotl32(x1, r); x1 ^= x0; }
    TF_RND(13) TF_RND(15) TF_RND(26) TF_RND(6)  x0 += ks1; x1 += ks2 + 1u;
    TF_RND(17) TF_RND(29) TF_RND(16) TF_RND(24) x0 += ks2; x1 += ks0 + 2u;
    TF_RND(13) TF_RND(15) TF_RND(26) TF_RND(6)  x0 += ks0; x1 += ks1 + 3u;
    TF_RND(17) TF_RND(29) TF_RND(16) TF_RND(24) x0 += ks1; x1 += ks2 + 4u;
    TF_RND(13) TF_RND(15) TF_RND(26) TF_RND(6)  x0 += ks2; x1 += ks0 + 5u;
#undef TF_RND
    o0 = x0; o1 = x1;
}
// Partitionable threefry: counter (0, idx); sample = XOR-fold of output words.
__device__ __forceinline__ float gumbel_at(int idx) {
    unsigned o0, o1;
    threefry_0_42(0u, (unsigned)idx, o0, o1);
    unsigned bits = o0 ^ o1;
    float u = __uint_as_float((bits >> 9) | 0x3f800000u) - 1.0f;
    const float tiny = 1.17549435e-38f;
    float r = fmaxf(tiny, u + tiny);
    return -logf(-logf(r));
}
__device__ __forceinline__ float gelu_exact(float v) {
    return 0.5f * v * (1.0f + erff(v * 0.70710678118654752f));
}
__device__ __forceinline__ float softplus_f(float v) {
    return fmaxf(v, 0.f) + log1pf(expf(-fabsf(v)));
}

#define GNT 1024
#define EPT 4

__global__ void __launch_bounds__(GNT) k_graph(
        const float* __restrict__ w1, const float* __restrict__ b1,
        const float* __restrict__ w2, const float* __restrict__ b2,
        const float* __restrict__ pbeta, const float* __restrict__ pgamma,
        const float* __restrict__ ptemp, float* __restrict__ outA) {
    __shared__ float sA[4096];
    __shared__ float sS[4096];
    __shared__ float ssq[64];
    __shared__ float sdinv[64];
    __shared__ unsigned long long smask[64];
    __shared__ float sw1[16], sb1[16], sw2[16];
    int tid = threadIdx.x;
    if (tid < 16) { sw1[tid] = w1[tid]; sb1[tid] = b1[tid]; sw2[tid] = w2[tid]; }
    float beta = *pbeta, gamma = *pgamma, b2v = *b2;
    float invt = 1.0f / fmaxf(*ptemp, 1e-6f);

#pragma unroll
    for (int k = 0; k < EPT; k++) sS[tid + GNT * k] = g_Z[tid + GNT * k];
    __syncthreads();
    if (tid < 64) {
        float s = 0.f;
#pragma unroll
        for (int m = 0; m < 64; m++) { float z = sS[tid * 64 + m]; s += z * z; }
        ssq[tid] = s;
    }
    __syncthreads();

    float d2r[EPT];
#pragma unroll
    for (int k = 0; k < EPT; k++) {
        int e = tid + GNT * k, i = e >> 6, j = e & 63;
        float dot = 0.f;
        for (int m = 0; m < 64; m++) dot += sS[i * 64 + m] * sS[j * 64 + m];
        float v = ssq[i] + ssq[j] - 2.0f * dot;
        d2r[k] = fmaxf(v, 0.f) * 0.5f;
        sA[e] = (i == j) ? 1.f : 0.f;
    }
    __syncthreads();

    for (int step = 0; step < 2; step++) {
#pragma unroll
        for (int k = 0; k < EPT; k++) {
            int e = tid + GNT * k;
            float a = sA[e] - 0.2f * d2r[k];
            float s = b2v;
#pragma unroll
            for (int m = 0; m < 16; m++) {
                float h = gelu_exact(fmaf(a, sw1[m], sb1[m]));
                s = fmaf(h, sw2[m], s);
            }
            a = a + beta * (softplus_f(s) * gamma);
            sA[e] = a;
        }
        __syncthreads();
        float r1[EPT], r2[EPT];
#pragma unroll
        for (int k = 0; k < EPT; k++) {
            int e = tid + GNT * k, i = e >> 6, j = e & 63;
            r1[k] = sA[e]; r2[k] = sA[j * 64 + i];
        }
        __syncthreads();
#pragma unroll
        for (int k = 0; k < EPT; k++) {
            int e = tid + GNT * k, i = e >> 6, j = e & 63;
            float v = 0.5f * (r1[k] + r2[k]);
            sA[e] = fmaxf(v, 0.f) + ((i == j) ? 1.f : 0.f);
        }
        __syncthreads();
    }

#pragma unroll
    for (int k = 0; k < EPT; k++) {
        int e = tid + GNT * k;
        sS[e] = (sA[e] + gumbel_at(e)) * invt;
    }
    __syncthreads();

    {   // warp-parallel top-16, 32 warps x 2 rows
        int warp = tid >> 5, lane = tid & 31;
        const float NEG_INF = __int_as_float(0xff800000);
#pragma unroll
        for (int rr = 0; rr < 2; rr++) {
            int r = warp * 2 + rr;
            float v0 = sS[r * 64 + lane];
            float v1 = sS[r * 64 + 32 + lane];
            bool p0 = false, p1 = false;
            for (int p = 0; p < 16; p++) {
                float bv; int bi;
                if (v0 >= v1) { bv = v0; bi = lane; }
                else          { bv = v1; bi = lane + 32; }
#pragma unroll
                for (int off = 16; off > 0; off >>= 1) {
                    float ov = __shfl_xor_sync(0xffffffffu, bv, off);
                    int   oi = __shfl_xor_sync(0xffffffffu, bi, off);
                    if (ov > bv || (ov == bv && oi < bi)) { bv = ov; bi = oi; }
                }
                if (bi == lane)           { p0 = true; v0 = NEG_INF; }
                else if (bi == lane + 32) { p1 = true; v1 = NEG_INF; }
            }
            unsigned lo = __ballot_sync(0xffffffffu, p0);
            unsigned hi = __ballot_sync(0xffffffffu, p1);
            if (lane == 0)
                smask[r] = (unsigned long long)lo | ((unsigned long long)hi << 32);
        }
    }
    __syncthreads();
#pragma unroll
    for (int k = 0; k < EPT; k++) {
        int e = tid + GNT * k, i = e >> 6, j = e & 63;
        if (!((smask[i] >> j) & 1ull)) sA[e] = 0.f;
    }
    __syncthreads();
    {
        float r1[EPT], r2[EPT];
#pragma unroll
        for (int k = 0; k < EPT; k++) {
            int e = tid + GNT * k, i = e >> 6, j = e & 63;
            r1[k] = sA[e]; r2[k] = sA[j * 64 + i];
        }
        __syncthreads();
#pragma unroll
        for (int k = 0; k < EPT; k++) {
            int e = tid + GNT * k, i = e >> 6, j = e & 63;
            float v = fmaxf(0.5f * (r1[k] + r2[k]), 0.f) + ((i == j) ? 1.f : 0.f);
            sA[e] = v;
        }
        __syncthreads();
    }
    if (tid < 64) {
        float s = 0.f;
        for (int j = 0; j < 64; j++) s += sA[tid * 64 + j];
        sdinv[tid] = rsqrtf(fmaxf(s, 1e-6f));
    }
    __syncthreads();
#pragma unroll
    for (int k = 0; k < EPT; k++) {
        int e = tid + GNT * k, i = e >> 6, j = e & 63;
        float v = sdinv[i] * sA[e] * sdinv[j] + ((i == j) ? 1.f : 0.f);
        sA[e] = v;
        outA[e] = v;
    }
    __syncthreads();
#pragma unroll
    for (int k = 0; k < EPT; k++) {
        int e = tid + GNT * k, i = e >> 6, j = e & 63;
        float s = 0.f;
        for (int m = 0; m < 64; m++) s += sA[i * 64 + m] * sA[m * 64 + j];
        g_A2[e] = s;
    }
}

// ================= Kernel 4: out = A2 @ x via WMMA bf16-split =================
// Padded smem strides to kill ldmatrix bank conflicts:
//   A stride 72 elems (144 B): row offsets mod 512B all distinct -> conflict-free
//   x-plane stride 264 elems (528 B): row offsets step 16 B mod 512 -> conflict-free
#define A_LD   72
#define X_LD   264
#define SMP_A  0
#define SMP_XH (128 * A_LD * 2)                    // 18432
#define SMP_XL (SMP_XH + 64 * X_LD * 2)            // 18432 + 33792 = 52224
#define SMP_TOT (SMP_XL + 64 * X_LD * 2)           // 86016

__global__ void __launch_bounds__(256) k_prop_wmma(const float* __restrict__ x,
                                                   float* __restrict__ out) {
    extern __shared__ char smem[];
    __nv_bfloat16* sA = reinterpret_cast<__nv_bfloat16*>(smem + SMP_A);
    __nv_bfloat16* sXH = reinterpret_cast<__nv_bfloat16*>(smem + SMP_XH);
    __nv_bfloat16* sXL = reinterpret_cast<__nv_bfloat16*>(smem + SMP_XL);
    int tid = threadIdx.x, warp = tid >> 5;
    int bw = blockIdx.x >> 2, tgrp = (blockIdx.x & 3) << 8;
    const float* xt = x + ((size_t)bw << 16) + tgrp;

    // A conversion: 4096 elements -> hi rows 0-63, lo rows 64-127 (stride A_LD)
#pragma unroll
    for (int k = 0; k < 16; k++) {
        int idx = tid + 256 * k;
        int c = idx >> 6, j = idx & 63;
        float a = g_A2[idx];
        __nv_bfloat16 ah = __float2bfloat16(a);
        __nv_bfloat16 al = __float2bfloat16(a - __bfloat162float(ah));
        sA[c * A_LD + j] = ah;
        sA[(c + 64) * A_LD + j] = al;
    }

    // x conversion: 4096 float4 -> hi/lo bf16 planes (stride X_LD)
#pragma unroll
    for (int r = 0; r < 16; r++) {
        int idx = tid + 256 * r;
        int j = idx >> 6, f4i = idx & 63;
        float4 v = *reinterpret_cast<const float4*>(xt + (size_t)j * 1024 + f4i * 4);
        __nv_bfloat16 h0 = __float2bfloat16(v.x), h1 = __float2bfloat16(v.y);
        __nv_bfloat16 h2 = __float2bfloat16(v.z), h3 = __float2bfloat16(v.w);
        __nv_bfloat16 l0 = __float2bfloat16(v.x - __bfloat162float(h0));
        __nv_bfloat16 l1 = __float2bfloat16(v.y - __bfloat162float(h1));
        __nv_bfloat16 l2 = __float2bfloat16(v.z - __bfloat162float(h2));
        __nv_bfloat16 l3 = __float2bfloat16(v.w - __bfloat162float(h3));
        __nv_bfloat162* ph = reinterpret_cast<__nv_bfloat162*>(sXH + j * X_LD + f4i * 4);
        __nv_bfloat162* pl = reinterpret_cast<__nv_bfloat162*>(sXL + j * X_LD + f4i * 4);
        ph[0] = __halves2bfloat162(h0, h1);
        ph[1] = __halves2bfloat162(h2, h3);
        pl[0] = __halves2bfloat162(l0, l1);
        pl[1] = __halves2bfloat162(l2, l3);
    }
    __syncthreads();

    size_t obase = (size_t)(bw >> 4) * 1048576 + (size_t)(bw & 15) * 1024 + tgrp;

    // Each warp: 2 N-tiles of 16 t
#pragma unroll
    for (int nt2 = 0; nt2 < 2; nt2++) {
        int n0 = (warp * 2 + nt2) * 16;
        wmma::fragment<wmma::accumulator, 16, 16, 16, float> acc[8];
#pragma unroll
        for (int mt = 0; mt < 8; mt++) wmma::fill_fragment(acc[mt], 0.0f);

#pragma unroll
        for (int k = 0; k < 4; k++) {
            wmma::fragment<wmma::matrix_a, 16, 16, 16, __nv_bfloat16, wmma::row_major> af[8];
#pragma unroll
            for (int mt = 0; mt < 8; mt++)
                wmma::load_matrix_sync(af[mt], sA + (mt * 16) * A_LD + k * 16, A_LD);

            wmma::fragment<wmma::matrix_b, 16, 16, 16, __nv_bfloat16, wmma::row_major> bh, bl;
            wmma::load_matrix_sync(bh, sXH + (k * 16) * X_LD + n0, X_LD);
            wmma::load_matrix_sync(bl, sXL + (k * 16) * X_LD + n0, X_LD);
#pragma unroll
            for (int mt = 0; mt < 8; mt++) wmma::mma_sync(acc[mt], af[mt], bh, acc[mt]);
#pragma unroll
            for (int mt = 0; mt < 8; mt++) wmma::mma_sync(acc[mt], af[mt], bl, acc[mt]);
        }

        // sum hi-part rows (mt) and lo-part rows (mt+4); store to gmem
#pragma unroll
        for (int mt = 0; mt < 4; mt++) {
#pragma unroll
            for (int e = 0; e < acc[mt].num_elements; e++)
                acc[mt].x[e] += acc[mt + 4].x[e];
            wmma::store_matrix_sync(out + obase + (size_t)(mt * 16) * 16384 + n0,
                                    acc[mt], 16384, wmma::mem_row_major);
        }
    }
}

// ================= launch =================
extern "C" void kernel_launch(void* const* d_in, const int* in_sizes, int n_in,
                              void* d_out, int out_size) {
    const float* x     = (const float*)d_in[0];
    const float* Wp    = (const float*)d_in[1];
    const float* w1    = (const float*)d_in[2];
    const float* b1    = (const float*)d_in[3];
    const float* w2    = (const float*)d_in[4];
    const float* b2    = (const float*)d_in[5];
    const float* beta  = (const float*)d_in[6];
    const float* gamma = (const float*)d_in[7];
    const float* temp  = (const float*)d_in[8];
    float* out = (float*)d_out;

    static int inited = 0;
    if (!inited) {
        cudaFuncSetAttribute(k_prop_wmma, cudaFuncAttributeMaxDynamicSharedMemorySize, SMP_TOT);
        inited = 1;
    }

    k_stats<<<8192, 256>>>(x);
    k_zmean<<<64, 256>>>(Wp);
    k_graph<<<1, GNT>>>(w1, b1, w2, b2, beta, gamma, temp, out + XR_ELEMS);
    k_prop_wmma<<<4096, 256, SMP_TOT>>>(x, out);
}